// round 15
// baseline (speedup 1.0000x reference)
#include <cuda_runtime.h>
#include <cuda_bf16.h>
#include <cuda_fp16.h>
#include <cstdint>

#define NMAX 100000
#define EMAX 1600000
#define DD   128

// ---------------- scratch ----------------------------------------------------
__device__ __half g_h16[(size_t)NMAX * DD];  // gemm output (fp16): dis[i]*(W in + b)
__device__ float  g_act[(size_t)NMAX * DD];  // agg output fp32 (next layer input)
__device__ float  g_dis[NMAX];               // (1+outdeg)^-0.5
__device__ int2   g_edge[EMAX];              // (row=src, col=dst)
__device__ int    g_indeg [NMAX];
__device__ int    g_rowdeg[NMAX];
__device__ int    g_ptr   [NMAX + 1];        // CSR by destination
__device__ int    g_cursor[NMAX];
__device__ int    g_csr_src[EMAX];
__device__ int    g_bsum[256];
__device__ int    g_boff[256];

// ---------------- prep -------------------------------------------------------
__global__ void k_zero(int n) {
    int i = blockIdx.x * blockDim.x + threadIdx.x;
    if (i < n) { g_indeg[i] = 0; g_rowdeg[i] = 0; }
}

__global__ void k_count(const int* __restrict__ ei, int e, int n) {
    int i = blockIdx.x * blockDim.x + threadIdx.x;
    if (i < e) {
        int r = ei[i];
        int c = ei[e + i];
        if ((unsigned)r >= (unsigned)n) r = 0;
        if ((unsigned)c >= (unsigned)n) c = 0;
        g_edge[i] = make_int2(r, c);
        atomicAdd(&g_rowdeg[r], 1);
        atomicAdd(&g_indeg[c], 1);
    }
}

__global__ void k_scan_block(int n) {
    __shared__ int s[1024];
    int i = blockIdx.x * 1024 + threadIdx.x;
    int v = (i < n) ? g_indeg[i] : 0;
    s[threadIdx.x] = v;
    __syncthreads();
    for (int off = 1; off < 1024; off <<= 1) {
        int t = 0;
        if (threadIdx.x >= off) t = s[threadIdx.x - off];
        __syncthreads();
        if (threadIdx.x >= off) s[threadIdx.x] += t;
        __syncthreads();
    }
    if (i < n) g_ptr[i] = s[threadIdx.x] - v;
    if (threadIdx.x == 1023 && blockIdx.x < 256) g_bsum[blockIdx.x] = s[1023];
}

__global__ void k_scan_top(int nb) {
    __shared__ int s[128];
    int v = (threadIdx.x < nb) ? g_bsum[threadIdx.x] : 0;
    s[threadIdx.x] = v;
    __syncthreads();
    for (int off = 1; off < 128; off <<= 1) {
        int t = 0;
        if (threadIdx.x >= off) t = s[threadIdx.x - off];
        __syncthreads();
        if (threadIdx.x >= off) s[threadIdx.x] += t;
        __syncthreads();
    }
    if (threadIdx.x < nb) g_boff[threadIdx.x] = s[threadIdx.x] - v;
}

// also computes dis (needs only rowdeg)
__global__ void k_scan_add(int n, int e) {
    int i = blockIdx.x * blockDim.x + threadIdx.x;
    if (i < n) {
        int p = g_ptr[i] + g_boff[i >> 10];
        g_ptr[i] = p;
        g_cursor[i] = p;
        g_dis[i] = rsqrtf(1.0f + (float)g_rowdeg[i]);
    }
    if (i == 0) g_ptr[n] = e;
}

__global__ void k_fill(int e) {
    int i = blockIdx.x * blockDim.x + threadIdx.x;
    if (i < e) {
        int2 rc = g_edge[i];
        int pos = atomicAdd(&g_cursor[rc.y], 1);
        g_csr_src[pos] = rc.x;
    }
}

// ---------------- TF32 helpers ----------------------------------------------
__device__ __forceinline__ uint32_t f2tf32(float f) {
    uint32_t r;
    asm("cvt.rna.tf32.f32 %0, %1;" : "=r"(r) : "f"(f));
    return r;
}
__device__ __forceinline__ float tf32f(float v) { return __uint_as_float(f2tf32(v)); }

__device__ __forceinline__ void mma_tf32(float c[4], const uint32_t a[4],
                                         const uint32_t b[2]) {
    asm volatile(
        "mma.sync.aligned.m16n8k8.row.col.f32.tf32.tf32.f32 "
        "{%0,%1,%2,%3}, {%4,%5,%6,%7}, {%8,%9}, {%0,%1,%2,%3};"
        : "+f"(c[0]), "+f"(c[1]), "+f"(c[2]), "+f"(c[3])
        : "r"(a[0]), "r"(a[1]), "r"(a[2]), "r"(a[3]), "r"(b[0]), "r"(b[1]));
}

// ---------------- GEMM (3xTF32, packed B fragments): g_h16 = dis*(in@W^T+b) --
// in_ext != nullptr : layer 1 (reads x).  nullptr : read g_act by symbol.
// Per 32-k chunk, W fragments are stored PACKED so the inner loop does ONE
// LDS.128 per (slice, n-tile): pk[((ss*16+nt)*32+lane)*4] = {hi(t),hi(t+4),
// lo(t),lo(t+4)} — same values as before, 4x fewer LDS instructions.
__global__ __launch_bounds__(256) void k_gemm(
    const float* __restrict__ in_ext, const float* __restrict__ W,
    const float* __restrict__ bias, int n)
{
    __shared__ float pk[8192];                 // 4 ss * 16 nt * 32 lanes * 4

    const int tid  = threadIdx.x;
    const int wid  = tid >> 5;
    const int lane = tid & 31;
    const int base = blockIdx.x * 128;
    const int g    = lane >> 2;
    const int t    = lane & 3;

    const int r0 = base + wid * 16 + g;
    const int r1 = r0 + 8;
    const bool ok0 = r0 < n, ok1 = r1 < n;
    const float s0 = ok0 ? g_dis[r0] : 0.f;
    const float s1 = ok1 ? g_dis[r1] : 0.f;
    const float* __restrict__ inp = in_ext ? in_ext : g_act;

    float acc[16][4];
#pragma unroll
    for (int nt = 0; nt < 16; nt++)
#pragma unroll
        for (int i = 0; i < 4; i++) acc[nt][i] = 0.0f;

    for (int kc = 0; kc < 4; kc++) {           // 32-wide K chunks
        // stage W[0:128][kc*32 .. +32] fragment-packed (hi/lo)
#pragma unroll
        for (int it = 0; it < 4; it++) {
            int idx = tid + it * 256;          // 0..1023
            int j = idx >> 3, q = idx & 7;     // j = out col, q = float4 within chunk
            float4 v = *(const float4*)(W + (size_t)j * DD + kc * 32 + q * 4);
            int ss = q >> 1, h = q & 1;
            int nt = j >> 3, gg = j & 7;
            float vv[4] = {v.x, v.y, v.z, v.w};
#pragma unroll
            for (int u = 0; u < 4; u++) {      // u = t
                float hi = tf32f(vv[u]);
                float lo = tf32f(vv[u] - hi);
                int b = ((ss * 16 + nt) * 32 + gg * 4 + u) * 4;
                pk[b + h]     = hi;
                pk[b + 2 + h] = lo;
            }
        }
        __syncthreads();

#pragma unroll
        for (int ss = 0; ss < 4; ss++) {       // k8 slices within chunk
            int k0 = kc * 32 + ss * 8;
            // A fragment (PTX formulas): a0=(r0,k0+t) a1=(r1,k0+t)
            //                            a2=(r0,k0+t+4) a3=(r1,k0+t+4)
            float av[4];
            av[0] = ok0 ? inp[(size_t)r0 * DD + k0 + t]     : 0.f;
            av[1] = ok1 ? inp[(size_t)r1 * DD + k0 + t]     : 0.f;
            av[2] = ok0 ? inp[(size_t)r0 * DD + k0 + t + 4] : 0.f;
            av[3] = ok1 ? inp[(size_t)r1 * DD + k0 + t + 4] : 0.f;
            uint32_t ahi[4], alo[4];
#pragma unroll
            for (int u = 0; u < 4; u++) {
                float hi = tf32f(av[u]);
                ahi[u] = __float_as_uint(hi);
                alo[u] = f2tf32(av[u] - hi);
            }

            const float* pks = pk + ss * 16 * 32 * 4 + lane * 4;
#pragma unroll
            for (int nt = 0; nt < 16; nt++) {
                float4 w = *(const float4*)(pks + nt * 32 * 4);
                uint32_t bhi[2] = {__float_as_uint(w.x), __float_as_uint(w.y)};
                uint32_t blo[2] = {__float_as_uint(w.z), __float_as_uint(w.w)};
                mma_tf32(acc[nt], ahi, bhi);
                mma_tf32(acc[nt], ahi, blo);
                mma_tf32(acc[nt], alo, bhi);
            }
        }
        __syncthreads();
    }

    // epilogue -> fp16 (half2 per n-tile)
#pragma unroll
    for (int nt = 0; nt < 16; nt++) {
        int j0 = nt * 8 + 2 * t;
        float2 bb = *(const float2*)(bias + j0);
        if (ok0) {
            __half2 o = __floats2half2_rn(s0 * (acc[nt][0] + bb.x),
                                          s0 * (acc[nt][1] + bb.y));
            *(__half2*)(g_h16 + (size_t)r0 * DD + j0) = o;
        }
        if (ok1) {
            __half2 o = __floats2half2_rn(s1 * (acc[nt][2] + bb.x),
                                          s1 * (acc[nt][3] + bb.y));
            *(__half2*)(g_h16 + (size_t)r1 * DD + j0) = o;
        }
    }
}

// ---------------- CSR aggregate (fp16 gather, fp32 accum) --------------------
// out[c] = relu(dis[c]*(h[c] + sum_in h[r])); one warp per destination.
__global__ __launch_bounds__(256) void k_agg(float4* __restrict__ out_ext, int n)
{
    int gt   = blockIdx.x * blockDim.x + threadIdx.x;
    int c    = gt >> 5;
    int lane = gt & 31;
    if (c >= n) return;

    const uint2* h2 = (const uint2*)g_h16;     // 4 halves per uint2; 32 per row
    float4 acc;
    {
        uint2 v = h2[(size_t)c * 32 + lane];   // self loop
        float2 f0 = __half22float2(*(__half2*)&v.x);
        float2 f1 = __half22float2(*(__half2*)&v.y);
        acc.x = f0.x; acc.y = f0.y; acc.z = f1.x; acc.w = f1.y;
    }
    int beg = g_ptr[c];
    int end = g_ptr[c + 1];

    for (int p = beg; p < end; p += 32) {
        int cnt = end - p; if (cnt > 32) cnt = 32;
        int myidx = (lane < cnt) ? __ldg(&g_csr_src[p + lane]) : 0;
#pragma unroll 4
        for (int j = 0; j < cnt; j++) {
            int r = __shfl_sync(0xffffffffu, myidx, j);
            uint2 v = h2[(size_t)r * 32 + lane];
            float2 f0 = __half22float2(*(__half2*)&v.x);
            float2 f1 = __half22float2(*(__half2*)&v.y);
            acc.x += f0.x; acc.y += f0.y; acc.z += f1.x; acc.w += f1.y;
        }
    }

    float s = g_dis[c];
    acc.x = fmaxf(acc.x * s, 0.f);
    acc.y = fmaxf(acc.y * s, 0.f);
    acc.z = fmaxf(acc.z * s, 0.f);
    acc.w = fmaxf(acc.w * s, 0.f);

    float4* out = out_ext ? out_ext : (float4*)g_act;
    out[(size_t)c * 32 + lane] = acc;
}

// ---------------- launcher ---------------------------------------------------
extern "C" void kernel_launch(void* const* d_in, const int* in_sizes, int n_in,
                              void* d_out, int out_size)
{
    const float* x = nullptr;
    const int* ei = nullptr;
    const float* Ws[3] = {nullptr, nullptr, nullptr};
    const float* bs[3] = {nullptr, nullptr, nullptr};
    int nx = 0, ne = 0, wi = 0, bi = 0;
    for (int i = 0; i < n_in; i++) {
        int sz = in_sizes[i];
        if (sz == DD * DD)       { if (wi < 3) Ws[wi++] = (const float*)d_in[i]; }
        else if (sz == DD)       { if (bi < 3) bs[bi++] = (const float*)d_in[i]; }
        else if (sz == 2 * EMAX) { ei = (const int*)d_in[i]; ne = sz; }
        else                     { x = (const float*)d_in[i]; nx = sz; }
    }
    if (!x || !ei || wi < 3 || bi < 3) {
        x  = (const float*)d_in[0];  nx = in_sizes[0];
        ei = (const int*)d_in[1];    ne = in_sizes[1];
        Ws[0] = (const float*)d_in[2]; bs[0] = (const float*)d_in[3];
        Ws[1] = (const float*)d_in[4]; bs[1] = (const float*)d_in[5];
        Ws[2] = (const float*)d_in[6]; bs[2] = (const float*)d_in[7];
    }

    int n = nx / DD;  if (n > NMAX) n = NMAX;
    int e = ne / 2;   if (e > EMAX) e = EMAX;

    const int T = 256;
    const int nb_scan = (n + 1023) / 1024;

    k_zero      <<<(n + T - 1) / T, T>>>(n);
    k_count     <<<(e + T - 1) / T, T>>>(ei, e, n);
    k_scan_block<<<nb_scan, 1024>>>(n);
    k_scan_top  <<<1, 128>>>(nb_scan);
    k_scan_add  <<<(n + T - 1) / T, T>>>(n, e);
    k_fill      <<<(e + T - 1) / T, T>>>(e);

    const int gemm_blocks = (n + 127) / 128;
    const int agg_blocks  = (int)(((long long)n * 32 + T - 1) / T);

    // layer 1: gemm reads x;  layers 2/3: nullptr -> kernel reads g_act by symbol
    k_gemm<<<gemm_blocks, 256>>>(x, Ws[0], bs[0], n);
    k_agg <<<agg_blocks, T>>>(nullptr, n);
    k_gemm<<<gemm_blocks, 256>>>(nullptr, Ws[1], bs[1], n);
    k_agg <<<agg_blocks, T>>>(nullptr, n);
    k_gemm<<<gemm_blocks, 256>>>(nullptr, Ws[2], bs[2], n);
    k_agg <<<agg_blocks, T>>>((float4*)d_out, n);
}

// round 17
// speedup vs baseline: 1.4883x; 1.4883x over previous
#include <cuda_runtime.h>
#include <cuda_bf16.h>
#include <cuda_fp16.h>
#include <cstdint>

#define NMAX 100000
#define EMAX 1600000
#define DD   128

// ---------------- scratch ----------------------------------------------------
__device__ __half g_h16[(size_t)NMAX * DD];  // gemm output (fp16): dis[i]*(W in + b)
__device__ float  g_act[(size_t)NMAX * DD];  // agg output fp32 (next layer input)
__device__ float  g_dis[NMAX];               // (1+outdeg)^-0.5
__device__ int2   g_edge[EMAX];              // (row=src, col=dst)
__device__ int    g_indeg [NMAX];
__device__ int    g_rowdeg[NMAX];
__device__ int    g_ptr   [NMAX + 1];        // CSR by destination
__device__ int    g_cursor[NMAX];
__device__ int    g_csr_src[EMAX];
__device__ int    g_bsum[256];
__device__ int    g_boff[256];

// ---------------- prep -------------------------------------------------------
__global__ void k_zero(int n) {
    int i = blockIdx.x * blockDim.x + threadIdx.x;
    if (i < n) { g_indeg[i] = 0; g_rowdeg[i] = 0; }
}

__global__ void k_count(const int* __restrict__ ei, int e, int n) {
    int i = blockIdx.x * blockDim.x + threadIdx.x;
    if (i < e) {
        int r = ei[i];
        int c = ei[e + i];
        if ((unsigned)r >= (unsigned)n) r = 0;
        if ((unsigned)c >= (unsigned)n) c = 0;
        g_edge[i] = make_int2(r, c);
        atomicAdd(&g_rowdeg[r], 1);
        atomicAdd(&g_indeg[c], 1);
    }
}

__global__ void k_scan_block(int n) {
    __shared__ int s[1024];
    int i = blockIdx.x * 1024 + threadIdx.x;
    int v = (i < n) ? g_indeg[i] : 0;
    s[threadIdx.x] = v;
    __syncthreads();
    for (int off = 1; off < 1024; off <<= 1) {
        int t = 0;
        if (threadIdx.x >= off) t = s[threadIdx.x - off];
        __syncthreads();
        if (threadIdx.x >= off) s[threadIdx.x] += t;
        __syncthreads();
    }
    if (i < n) g_ptr[i] = s[threadIdx.x] - v;
    if (threadIdx.x == 1023 && blockIdx.x < 256) g_bsum[blockIdx.x] = s[1023];
}

__global__ void k_scan_top(int nb) {
    __shared__ int s[128];
    int v = (threadIdx.x < nb) ? g_bsum[threadIdx.x] : 0;
    s[threadIdx.x] = v;
    __syncthreads();
    for (int off = 1; off < 128; off <<= 1) {
        int t = 0;
        if (threadIdx.x >= off) t = s[threadIdx.x - off];
        __syncthreads();
        if (threadIdx.x >= off) s[threadIdx.x] += t;
        __syncthreads();
    }
    if (threadIdx.x < nb) g_boff[threadIdx.x] = s[threadIdx.x] - v;
}

// also computes dis (needs only rowdeg)
__global__ void k_scan_add(int n, int e) {
    int i = blockIdx.x * blockDim.x + threadIdx.x;
    if (i < n) {
        int p = g_ptr[i] + g_boff[i >> 10];
        g_ptr[i] = p;
        g_cursor[i] = p;
        g_dis[i] = rsqrtf(1.0f + (float)g_rowdeg[i]);
    }
    if (i == 0) g_ptr[n] = e;
}

__global__ void k_fill(int e) {
    int i = blockIdx.x * blockDim.x + threadIdx.x;
    if (i < e) {
        int2 rc = g_edge[i];
        int pos = atomicAdd(&g_cursor[rc.y], 1);
        g_csr_src[pos] = rc.x;
    }
}

// ---------------- BF16 helpers -----------------------------------------------
__device__ __forceinline__ float bf16f(float v) {
    return __bfloat162float(__float2bfloat16_rn(v));
}
// pack (a, b) -> bf16x2 (a in low half)
__device__ __forceinline__ uint32_t pack_bf2(float a, float b) {
    __nv_bfloat162 p = __floats2bfloat162_rn(a, b);
    return *(uint32_t*)&p;
}

__device__ __forceinline__ void mma_bf16(float c[4], const uint32_t a[4],
                                         const uint32_t b[2]) {
    asm volatile(
        "mma.sync.aligned.m16n8k16.row.col.f32.bf16.bf16.f32 "
        "{%0,%1,%2,%3}, {%4,%5,%6,%7}, {%8,%9}, {%0,%1,%2,%3};"
        : "+f"(c[0]), "+f"(c[1]), "+f"(c[2]), "+f"(c[3])
        : "r"(a[0]), "r"(a[1]), "r"(a[2]), "r"(a[3]), "r"(b[0]), "r"(b[1]));
}

// ---------------- GEMM (2xBF16 split, m16n8k16): g_h16 = dis*(in@W^T + b) ----
// Structure identical to the proven R14 kernel; only the mma dtype/K changed.
// in_ext != nullptr : layer 1 (reads x).  nullptr : read g_act by symbol.
// W staged per 64-k chunk as PACKED bf16x2 hi/lo: wb[j*36 + p] = cols (2p,2p+1)
// of row j (local pair p = 0..31). Compute-read bank = 4g+t: conflict-free.
__global__ __launch_bounds__(256) void k_gemm(
    const float* __restrict__ in_ext, const float* __restrict__ W,
    const float* __restrict__ bias, int n)
{
    __shared__ uint32_t wb_hi[128 * 36];
    __shared__ uint32_t wb_lo[128 * 36];

    const int tid  = threadIdx.x;
    const int wid  = tid >> 5;
    const int lane = tid & 31;
    const int base = blockIdx.x * 128;
    const int g    = lane >> 2;
    const int t    = lane & 3;

    const int r0 = base + wid * 16 + g;
    const int r1 = r0 + 8;
    const bool ok0 = r0 < n, ok1 = r1 < n;
    const float s0 = ok0 ? g_dis[r0] : 0.f;
    const float s1 = ok1 ? g_dis[r1] : 0.f;
    const float* __restrict__ inp = in_ext ? in_ext : g_act;

    float acc[16][4];
#pragma unroll
    for (int nt = 0; nt < 16; nt++)
#pragma unroll
        for (int i = 0; i < 4; i++) acc[nt][i] = 0.0f;

    for (int kc = 0; kc < 2; kc++) {           // 64-wide K chunks
        // stage W[0:128][kc*64 : +64] as packed bf16x2 hi/lo
#pragma unroll
        for (int it = 0; it < 8; it++) {
            int idx = tid + it * 256;          // 0..2047
            int j = idx >> 4, q4 = idx & 15;   // q4 = float4 within 64-float chunk
            float4 v = *(const float4*)(W + (size_t)j * DD + kc * 64 + q4 * 4);
            float hx = bf16f(v.x), hy = bf16f(v.y);
            float hz = bf16f(v.z), hw = bf16f(v.w);
            int b = j * 36 + q4 * 2;
            wb_hi[b]     = pack_bf2(hx, hy);
            wb_hi[b + 1] = pack_bf2(hz, hw);
            wb_lo[b]     = pack_bf2(v.x - hx, v.y - hy);
            wb_lo[b + 1] = pack_bf2(v.z - hz, v.w - hw);
        }
        __syncthreads();

#pragma unroll
        for (int ss = 0; ss < 4; ss++) {       // k16 slices within chunk
            int k0 = kc * 64 + ss * 16;
            // A fragments (PTX m16n8k16): a0=(r0, 2t:2t+1) a1=(r1, 2t:2t+1)
            //                             a2=(r0, 2t+8:2t+9) a3=(r1, 2t+8:2t+9)
            float2 z = make_float2(0.f, 0.f);
            float2 p00 = ok0 ? *(const float2*)(inp + (size_t)r0 * DD + k0 + 2 * t)     : z;
            float2 p10 = ok1 ? *(const float2*)(inp + (size_t)r1 * DD + k0 + 2 * t)     : z;
            float2 p01 = ok0 ? *(const float2*)(inp + (size_t)r0 * DD + k0 + 2 * t + 8) : z;
            float2 p11 = ok1 ? *(const float2*)(inp + (size_t)r1 * DD + k0 + 2 * t + 8) : z;

            uint32_t ahi[4], alo[4];
            {
                float h;
                h = bf16f(p00.x); float h2 = bf16f(p00.y);
                ahi[0] = pack_bf2(h, h2);  alo[0] = pack_bf2(p00.x - h, p00.y - h2);
                h = bf16f(p10.x); h2 = bf16f(p10.y);
                ahi[1] = pack_bf2(h, h2);  alo[1] = pack_bf2(p10.x - h, p10.y - h2);
                h = bf16f(p01.x); h2 = bf16f(p01.y);
                ahi[2] = pack_bf2(h, h2);  alo[2] = pack_bf2(p01.x - h, p01.y - h2);
                h = bf16f(p11.x); h2 = bf16f(p11.y);
                ahi[3] = pack_bf2(h, h2);  alo[3] = pack_bf2(p11.x - h, p11.y - h2);
            }

#pragma unroll
            for (int nt = 0; nt < 16; nt++) {
                // B fragment: b0 = rows (2t,2t+1) col nt*8+g -> pair ss*8+t
                //             b1 = rows (2t+8,2t+9)          -> pair ss*8+t+4
                int c = (nt * 8 + g) * 36 + ss * 8 + t;
                uint32_t bhi[2] = {wb_hi[c], wb_hi[c + 4]};
                uint32_t blo[2] = {wb_lo[c], wb_lo[c + 4]};
                mma_bf16(acc[nt], ahi, bhi);
                mma_bf16(acc[nt], ahi, blo);
                mma_bf16(acc[nt], alo, bhi);
            }
        }
        __syncthreads();
    }

    // epilogue -> fp16 (half2 per n-tile); C layout: c0=(r0,2t) c1=(r0,2t+1)
    //                                                c2=(r1,2t) c3=(r1,2t+1)
#pragma unroll
    for (int nt = 0; nt < 16; nt++) {
        int j0 = nt * 8 + 2 * t;
        float2 bb = *(const float2*)(bias + j0);
        if (ok0) {
            __half2 o = __floats2half2_rn(s0 * (acc[nt][0] + bb.x),
                                          s0 * (acc[nt][1] + bb.y));
            *(__half2*)(g_h16 + (size_t)r0 * DD + j0) = o;
        }
        if (ok1) {
            __half2 o = __floats2half2_rn(s1 * (acc[nt][2] + bb.x),
                                          s1 * (acc[nt][3] + bb.y));
            *(__half2*)(g_h16 + (size_t)r1 * DD + j0) = o;
        }
    }
}

// ---------------- CSR aggregate (fp16 gather, fp32 accum) --------------------
// out[c] = relu(dis[c]*(h[c] + sum_in h[r])); one warp per destination.
__global__ __launch_bounds__(256) void k_agg(float4* __restrict__ out_ext, int n)
{
    int gt   = blockIdx.x * blockDim.x + threadIdx.x;
    int c    = gt >> 5;
    int lane = gt & 31;
    if (c >= n) return;

    const uint2* h2 = (const uint2*)g_h16;     // 4 halves per uint2; 32 per row
    float4 acc;
    {
        uint2 v = h2[(size_t)c * 32 + lane];   // self loop
        float2 f0 = __half22float2(*(__half2*)&v.x);
        float2 f1 = __half22float2(*(__half2*)&v.y);
        acc.x = f0.x; acc.y = f0.y; acc.z = f1.x; acc.w = f1.y;
    }
    int beg = g_ptr[c];
    int end = g_ptr[c + 1];

    for (int p = beg; p < end; p += 32) {
        int cnt = end - p; if (cnt > 32) cnt = 32;
        int myidx = (lane < cnt) ? __ldg(&g_csr_src[p + lane]) : 0;
#pragma unroll 4
        for (int j = 0; j < cnt; j++) {
            int r = __shfl_sync(0xffffffffu, myidx, j);
            uint2 v = h2[(size_t)r * 32 + lane];
            float2 f0 = __half22float2(*(__half2*)&v.x);
            float2 f1 = __half22float2(*(__half2*)&v.y);
            acc.x += f0.x; acc.y += f0.y; acc.z += f1.x; acc.w += f1.y;
        }
    }

    float s = g_dis[c];
    acc.x = fmaxf(acc.x * s, 0.f);
    acc.y = fmaxf(acc.y * s, 0.f);
    acc.z = fmaxf(acc.z * s, 0.f);
    acc.w = fmaxf(acc.w * s, 0.f);

    float4* out = out_ext ? out_ext : (float4*)g_act;
    out[(size_t)c * 32 + lane] = acc;
}

// ---------------- launcher ---------------------------------------------------
extern "C" void kernel_launch(void* const* d_in, const int* in_sizes, int n_in,
                              void* d_out, int out_size)
{
    const float* x = nullptr;
    const int* ei = nullptr;
    const float* Ws[3] = {nullptr, nullptr, nullptr};
    const float* bs[3] = {nullptr, nullptr, nullptr};
    int nx = 0, ne = 0, wi = 0, bi = 0;
    for (int i = 0; i < n_in; i++) {
        int sz = in_sizes[i];
        if (sz == DD * DD)       { if (wi < 3) Ws[wi++] = (const float*)d_in[i]; }
        else if (sz == DD)       { if (bi < 3) bs[bi++] = (const float*)d_in[i]; }
        else if (sz == 2 * EMAX) { ei = (const int*)d_in[i]; ne = sz; }
        else                     { x = (const float*)d_in[i]; nx = sz; }
    }
    if (!x || !ei || wi < 3 || bi < 3) {
        x  = (const float*)d_in[0];  nx = in_sizes[0];
        ei = (const int*)d_in[1];    ne = in_sizes[1];
        Ws[0] = (const float*)d_in[2]; bs[0] = (const float*)d_in[3];
        Ws[1] = (const float*)d_in[4]; bs[1] = (const float*)d_in[5];
        Ws[2] = (const float*)d_in[6]; bs[2] = (const float*)d_in[7];
    }

    int n = nx / DD;  if (n > NMAX) n = NMAX;
    int e = ne / 2;   if (e > EMAX) e = EMAX;

    const int T = 256;
    const int nb_scan = (n + 1023) / 1024;

    k_zero      <<<(n + T - 1) / T, T>>>(n);
    k_count     <<<(e + T - 1) / T, T>>>(ei, e, n);
    k_scan_block<<<nb_scan, 1024>>>(n);
    k_scan_top  <<<1, 128>>>(nb_scan);
    k_scan_add  <<<(n + T - 1) / T, T>>>(n, e);
    k_fill      <<<(e + T - 1) / T, T>>>(e);

    const int gemm_blocks = (n + 127) / 128;
    const int agg_blocks  = (int)(((long long)n * 32 + T - 1) / T);

    // layer 1: gemm reads x;  layers 2/3: nullptr -> kernel reads g_act by symbol
    k_gemm<<<gemm_blocks, 256>>>(x, Ws[0], bs[0], n);
    k_agg <<<agg_blocks, T>>>(nullptr, n);
    k_gemm<<<gemm_blocks, 256>>>(nullptr, Ws[1], bs[1], n);
    k_agg <<<agg_blocks, T>>>(nullptr, n);
    k_gemm<<<gemm_blocks, 256>>>(nullptr, Ws[2], bs[2], n);
    k_agg <<<agg_blocks, T>>>((float4*)d_out, n);
}